// round 7
// baseline (speedup 1.0000x reference)
#include <cuda_runtime.h>
#include <cuda_bf16.h>
#include <math.h>
#include <stdint.h>

#define TOKENS 4096
#define DM     1024
#define DFF    4096
#define HEADS  16
#define DK     64
#define SEQ    2048
#define BATCH  2

// ---------------- scratch (device globals) --------------------------------
__device__ float g_T1[TOKENS * DM];
__device__ float g_AO[TOKENS * DM];
__device__ __nv_bfloat16 g_Xh[TOKENS * DM],  g_Xl[TOKENS * DM];
__device__ __nv_bfloat16 g_Qh[TOKENS * DM],  g_Ql[TOKENS * DM];
__device__ __nv_bfloat16 g_Kh[TOKENS * DM],  g_Kl[TOKENS * DM];
__device__ __nv_bfloat16 g_Vh[TOKENS * DM],  g_Vl[TOKENS * DM];
__device__ __nv_bfloat16 g_Ch[TOKENS * DM],  g_Cl[TOKENS * DM];
__device__ __nv_bfloat16 g_AOh[TOKENS * DM], g_AOl[TOKENS * DM];
__device__ __nv_bfloat16 g_Hh[TOKENS * DFF], g_Hl[TOKENS * DFF];
__device__ __nv_bfloat16 g_Wh[4 * DM * DM + 2 * DM * DFF];
__device__ __nv_bfloat16 g_Wl[4 * DM * DM + 2 * DM * DFF];
__device__ unsigned char g_MB[BATCH * SEQ * SEQ / 8];

// ---------------- ptx helpers ---------------------------------------------
__device__ __forceinline__ uint32_t smem_u32(const void* p) {
    uint32_t a;
    asm("{ .reg .u64 t; cvta.to.shared.u64 t, %1; cvt.u32.u64 %0, t; }" : "=r"(a) : "l"(p));
    return a;
}
__device__ __forceinline__ void ldm_x4(uint32_t* r, uint32_t a) {
    asm volatile("ldmatrix.sync.aligned.m8n8.x4.shared.b16 {%0,%1,%2,%3}, [%4];"
        : "=r"(r[0]), "=r"(r[1]), "=r"(r[2]), "=r"(r[3]) : "r"(a));
}
__device__ __forceinline__ void ldm_x2(uint32_t* r, uint32_t a) {
    asm volatile("ldmatrix.sync.aligned.m8n8.x2.shared.b16 {%0,%1}, [%2];"
        : "=r"(r[0]), "=r"(r[1]) : "r"(a));
}
__device__ __forceinline__ void ldm_x2t(uint32_t* r, uint32_t a) {
    asm volatile("ldmatrix.sync.aligned.m8n8.x2.trans.shared.b16 {%0,%1}, [%2];"
        : "=r"(r[0]), "=r"(r[1]) : "r"(a));
}
__device__ __forceinline__ void mma16816(float* c, const uint32_t* a, const uint32_t* b) {
    asm volatile("mma.sync.aligned.m16n8k16.row.col.f32.bf16.bf16.f32 "
        "{%0,%1,%2,%3}, {%4,%5,%6,%7}, {%8,%9}, {%0,%1,%2,%3};"
        : "+f"(c[0]), "+f"(c[1]), "+f"(c[2]), "+f"(c[3])
        : "r"(a[0]), "r"(a[1]), "r"(a[2]), "r"(a[3]), "r"(b[0]), "r"(b[1]));
}
__device__ __forceinline__ void cpasync16(uint32_t s, const void* g) {
    asm volatile("cp.async.cg.shared.global [%0], [%1], 16;" :: "r"(s), "l"(g));
}
__device__ __forceinline__ void cpasync8(uint32_t s, const void* g) {
    asm volatile("cp.async.ca.shared.global [%0], [%1], 8;" :: "r"(s), "l"(g));
}
#define CP_COMMIT() asm volatile("cp.async.commit_group;" ::: "memory")
#define CP_WAIT(n)  asm volatile("cp.async.wait_group %0;" :: "n"(n) : "memory")

__device__ __forceinline__ float gelu_exact(float x) {
    return 0.5f * x * (1.0f + erff(x * 0.70710678118654752f));
}
__device__ __forceinline__ void pack_hl(float x, float y, uint32_t& h, uint32_t& l) {
    __nv_bfloat162 hh = __floats2bfloat162_rn(x, y);
    __nv_bfloat162 ll = __floats2bfloat162_rn(x - __bfloat162float(hh.x),
                                              y - __bfloat162float(hh.y));
    h = reinterpret_cast<uint32_t&>(hh);
    l = reinterpret_cast<uint32_t&>(ll);
}

// ---------------- small prep kernels --------------------------------------
__global__ __launch_bounds__(256) void split_kernel(
    const float4* __restrict__ X, __nv_bfloat16* __restrict__ H, __nv_bfloat16* __restrict__ L)
{
    int i = blockIdx.x * 256 + threadIdx.x;
    float4 v = X[i];
    uint32_t h0, l0, h1, l1;
    pack_hl(v.x, v.y, h0, l0);
    pack_hl(v.z, v.w, h1, l1);
    ((uint32_t*)H)[2 * i] = h0; ((uint32_t*)H)[2 * i + 1] = h1;
    ((uint32_t*)L)[2 * i] = l0; ((uint32_t*)L)[2 * i + 1] = l1;
}

__global__ __launch_bounds__(256) void maskbits_kernel(
    const unsigned char* __restrict__ m, unsigned char* __restrict__ bits)
{
    int i = blockIdx.x * 256 + threadIdx.x;
    unsigned long long v = *(const unsigned long long*)(m + 8ull * i);
    unsigned r = 0;
#pragma unroll
    for (int j = 0; j < 8; j++)
        r |= (((v >> (8 * j)) & 0xffull) ? 1u : 0u) << j;
    bits[i] = (unsigned char)r;
}

// W [K,N] fp32 -> Th/Tl [N,K] bf16 (transpose + split)
__device__ __forceinline__ void splitT_body(const float* __restrict__ W,
    __nv_bfloat16* __restrict__ Th, __nv_bfloat16* __restrict__ Tl, int K, int N)
{
    __shared__ float t[32][33];
    int n0 = blockIdx.x << 5, k0 = blockIdx.y << 5;
    int tx = threadIdx.x, ty = threadIdx.y;
#pragma unroll
    for (int i = 0; i < 4; i++)
        t[ty + 8 * i][tx] = W[(size_t)(k0 + ty + 8 * i) * N + n0 + tx];
    __syncthreads();
#pragma unroll
    for (int i = 0; i < 4; i++) {
        float v = t[tx][ty + 8 * i];
        __nv_bfloat16 hv = __float2bfloat16(v);
        size_t o = (size_t)(n0 + ty + 8 * i) * K + k0 + tx;
        Th[o] = hv;
        Tl[o] = __float2bfloat16(v - __bfloat162float(hv));
    }
}
__global__ void splitT_kernel(const float* __restrict__ W,
    __nv_bfloat16* __restrict__ Th, __nv_bfloat16* __restrict__ Tl, int K, int N)
{
    splitT_body(W, Th, Tl, K, N);
}
// 3 square weights in one launch (z selects); keeps attn at launch index 5
__global__ void splitT3_kernel(const float* __restrict__ W0, const float* __restrict__ W1,
    const float* __restrict__ W2, __nv_bfloat16* __restrict__ Th, __nv_bfloat16* __restrict__ Tl)
{
    int z = blockIdx.z;
    const float* W = (z == 0) ? W0 : (z == 1) ? W1 : W2;
    splitT_body(W, Th + (size_t)z * DM * DM, Tl + (size_t)z * DM * DM, DM, DM);
}

// ===== mma.sync split-bf16 GEMM: C[M,N] = A@B^T (+epi), B stored [N,K] ====
// BK=32 (64B rows, SW64 swizzle), double-buffered, 64KB smem -> 2 CTAs/SM
#define TILE_B 8192
#define BUF_B  32768
#define SM_TOT 65536
// EPI: 0 bias, 1 bias+gelu, 2 bias+residual.  OM: 0 fp32 C, 1 bf16 hi/lo pair
template <int EPI, int OM>
__global__ __launch_bounds__(256, 2) void gemm3_kernel(
    const __nv_bfloat16* __restrict__ Ah, const __nv_bfloat16* __restrict__ Al,
    const __nv_bfloat16* __restrict__ Bh, const __nv_bfloat16* __restrict__ Bl,
    const float* __restrict__ bias, const float* __restrict__ Rres,
    float* __restrict__ C, __nv_bfloat16* __restrict__ Ch, __nv_bfloat16* __restrict__ Cl,
    int N, int K)
{
    extern __shared__ char gsm[];
    uint32_t sb = smem_u32(gsm);
    int tid = threadIdx.x, wid = tid >> 5, lane = tid & 31;
    int rowBase = blockIdx.y * 128, colBase = blockIdx.x * 128;
    int warp_m = (wid & 1) * 64, warp_n = (wid >> 1) * 32;

    float acc[4][4][4];
#pragma unroll
    for (int i = 0; i < 4; i++)
#pragma unroll
        for (int j = 0; j < 4; j++)
#pragma unroll
            for (int e = 0; e < 4; e++) acc[i][j][e] = 0.0f;

    const int NC = K >> 5;
    auto issue = [&](int c) {
        int k0 = c << 5, buf = c & 1;
#pragma unroll
        for (int i = 0; i < 8; i++) {
            int t = i >> 1;
            int e = ((i & 1) << 8) + tid;
            int row = e >> 2, seg = e & 3;
            const __nv_bfloat16* src = (t == 0) ? Ah : (t == 1) ? Al : (t == 2) ? Bh : Bl;
            int gr = ((t < 2) ? rowBase : colBase) + row;
            int off = row * 64 + seg * 16;
            off ^= (off >> 3) & 0x30;
            cpasync16(sb + buf * BUF_B + t * TILE_B + off,
                      src + (size_t)gr * K + k0 + seg * 8);
        }
        CP_COMMIT();
    };

    issue(0);
    int a_lrow = lane & 15, a_kadd = (lane < 16) ? 0 : 16;
    int b_lrow = lane & 7, b_kadd = ((lane & 15) >= 8) ? 16 : 0;

    for (int c = 0; c < NC; c++) {
        if (c + 1 < NC) { issue(c + 1); CP_WAIT(1); }
        else CP_WAIT(0);
        __syncthreads();
        uint32_t base = sb + (c & 1) * BUF_B;
#pragma unroll
        for (int ks = 0; ks < 1; ks++) {   // BK=32 -> single k16-pair handled below
        }
#pragma unroll
        for (int ks = 0; ks < 2; ks++) {
            uint32_t aH[4][4], aL[4][4];
#pragma unroll
            for (int i = 0; i < 4; i++) {
                int off = (warp_m + 16 * i + a_lrow) * 64 + a_kadd;
                // note: BK=32 holds exactly one k16 per ks? -> ks selects 16B pair
                off += ks * 32;
                off ^= (off >> 3) & 0x30;
                ldm_x4(aH[i], base + off);
                ldm_x4(aL[i], base + TILE_B + off);
            }
#pragma unroll
            for (int j = 0; j < 4; j++) {
                int off = (warp_n + 8 * j + b_lrow) * 64 + ks * 32 + b_kadd;
                off ^= (off >> 3) & 0x30;
                uint32_t bH[2], bL[2];
                ldm_x2(bH, base + 2 * TILE_B + off);
                ldm_x2(bL, base + 3 * TILE_B + off);
#pragma unroll
                for (int i = 0; i < 4; i++) {
                    mma16816(acc[i][j], aH[i], bH);
                    mma16816(acc[i][j], aH[i], bL);
                    mma16816(acc[i][j], aL[i], bH);
                }
            }
        }
        __syncthreads();
    }

    int quad = lane >> 2, pos = lane & 3;
#pragma unroll
    for (int i = 0; i < 4; i++)
#pragma unroll
        for (int j = 0; j < 4; j++) {
            int col = colBase + warp_n + 8 * j + 2 * pos;
            float2 bz = *(const float2*)&bias[col];
#pragma unroll
            for (int h = 0; h < 2; h++) {
                size_t row = rowBase + warp_m + 16 * i + quad + 8 * h;
                float vx = acc[i][j][2 * h] + bz.x;
                float vy = acc[i][j][2 * h + 1] + bz.y;
                if (EPI == 2) {
                    float2 rv = *(const float2*)&Rres[row * N + col];
                    vx += rv.x; vy += rv.y;
                }
                if (EPI == 1) { vx = gelu_exact(vx); vy = gelu_exact(vy); }
                if (OM == 0) {
                    *(float2*)&C[row * N + col] = make_float2(vx, vy);
                } else {
                    uint32_t hw, lw;
                    pack_hl(vx, vy, hw, lw);
                    ((uint32_t*)Ch)[(row * N + col) >> 1] = hw;
                    ((uint32_t*)Cl)[(row * N + col) >> 1] = lw;
                }
            }
        }
}

// ===== fused QKV GEMM (same mainloop, per-block output select) ============
__global__ __launch_bounds__(256, 2) void gemm_qkv_kernel(
    const __nv_bfloat16* __restrict__ Ah, const __nv_bfloat16* __restrict__ Al,
    const __nv_bfloat16* __restrict__ Bh, const __nv_bfloat16* __restrict__ Bl,
    const float* __restrict__ bq, const float* __restrict__ bk, const float* __restrict__ bv,
    __nv_bfloat16* __restrict__ Qh, __nv_bfloat16* __restrict__ Ql,
    __nv_bfloat16* __restrict__ Kh, __nv_bfloat16* __restrict__ Kl,
    __nv_bfloat16* __restrict__ Vh, __nv_bfloat16* __restrict__ Vl)
{
    const int K = DM;
    extern __shared__ char gsm[];
    uint32_t sb = smem_u32(gsm);
    int tid = threadIdx.x, wid = tid >> 5, lane = tid & 31;
    int rowBase = blockIdx.y * 128, colBase = blockIdx.x * 128;
    int warp_m = (wid & 1) * 64, warp_n = (wid >> 1) * 32;

    float acc[4][4][4];
#pragma unroll
    for (int i = 0; i < 4; i++)
#pragma unroll
        for (int j = 0; j < 4; j++)
#pragma unroll
            for (int e = 0; e < 4; e++) acc[i][j][e] = 0.0f;

    const int NC = K >> 5;
    auto issue = [&](int c) {
        int k0 = c << 5, buf = c & 1;
#pragma unroll
        for (int i = 0; i < 8; i++) {
            int t = i >> 1;
            int e = ((i & 1) << 8) + tid;
            int row = e >> 2, seg = e & 3;
            const __nv_bfloat16* src = (t == 0) ? Ah : (t == 1) ? Al : (t == 2) ? Bh : Bl;
            int gr = ((t < 2) ? rowBase : colBase) + row;
            int off = row * 64 + seg * 16;
            off ^= (off >> 3) & 0x30;
            cpasync16(sb + buf * BUF_B + t * TILE_B + off,
                      src + (size_t)gr * K + k0 + seg * 8);
        }
        CP_COMMIT();
    };

    issue(0);
    int a_lrow = lane & 15, a_kadd = (lane < 16) ? 0 : 16;
    int b_lrow = lane & 7, b_kadd = ((lane & 15) >= 8) ? 16 : 0;

    for (int c = 0; c < NC; c++) {
        if (c + 1 < NC) { issue(c + 1); CP_WAIT(1); }
        else CP_WAIT(0);
        __syncthreads();
        uint32_t base = sb + (c & 1) * BUF_B;
#pragma unroll
        for (int ks = 0; ks < 2; ks++) {
            uint32_t aH[4][4], aL[4][4];
#pragma unroll
            for (int i = 0; i < 4; i++) {
                int off = (warp_m + 16 * i + a_lrow) * 64 + ks * 32 + a_kadd;
                off ^= (off >> 3) & 0x30;
                ldm_x4(aH[i], base + off);
                ldm_x4(aL[i], base + TILE_B + off);
            }
#pragma unroll
            for (int j = 0; j < 4; j++) {
                int off = (warp_n + 8 * j + b_lrow) * 64 + ks * 32 + b_kadd;
                off ^= (off >> 3) & 0x30;
                uint32_t bH[2], bL[2];
                ldm_x2(bH, base + 2 * TILE_B + off);
                ldm_x2(bL, base + 3 * TILE_B + off);
#pragma unroll
                for (int i = 0; i < 4; i++) {
                    mma16816(acc[i][j], aH[i], bH);
                    mma16816(acc[i][j], aH[i], bL);
                    mma16816(acc[i][j], aL[i], bH);
                }
            }
        }
        __syncthreads();
    }

    int sel = colBase >> 10;
    const float* bias = (sel == 0) ? bq : (sel == 1) ? bk : bv;
    __nv_bfloat16* Oh = (sel == 0) ? Qh : (sel == 1) ? Kh : Vh;
    __nv_bfloat16* Ol = (sel == 0) ? Ql : (sel == 1) ? Kl : Vl;

    int quad = lane >> 2, pos = lane & 3;
#pragma unroll
    for (int i = 0; i < 4; i++)
#pragma unroll
        for (int j = 0; j < 4; j++) {
            int col = (colBase & 1023) + warp_n + 8 * j + 2 * pos;
            float2 bz = *(const float2*)&bias[col];
#pragma unroll
            for (int h = 0; h < 2; h++) {
                size_t row = rowBase + warp_m + 16 * i + quad + 8 * h;
                uint32_t hw, lw;
                pack_hl(acc[i][j][2 * h] + bz.x, acc[i][j][2 * h + 1] + bz.y, hw, lw);
                ((uint32_t*)Oh)[(row * DM + col) >> 1] = hw;
                ((uint32_t*)Ol)[(row * DM + col) >> 1] = lw;
            }
        }
}

// ======== tensor-core flash attention (split bf16, online softmax) ========
#define AQ    32768
#define ABUF  33792
#define ASM   (AQ + 2 * ABUF)
__global__ void __launch_bounds__(256, 2) attn_kernel(
    const __nv_bfloat16* __restrict__ Qh_, const __nv_bfloat16* __restrict__ Ql_,
    const __nv_bfloat16* __restrict__ Kh_, const __nv_bfloat16* __restrict__ Kl_,
    const __nv_bfloat16* __restrict__ Vh_, const __nv_bfloat16* __restrict__ Vl_,
    const unsigned char* __restrict__ MB,
    __nv_bfloat16* __restrict__ Ch_, __nv_bfloat16* __restrict__ Cl_)
{
    extern __shared__ char sm[];
    uint32_t sb = smem_u32(sm);
    int tid = threadIdx.x, w = tid >> 5, lane = tid & 31;
    int quad = lane >> 2, pos = lane & 3;
    int q0 = blockIdx.x * 128, h = blockIdx.y, b = blockIdx.z;
    size_t qrow0 = (size_t)b * SEQ + q0;
    const float scale = 0.125f;

#pragma unroll
    for (int i = 0; i < 8; i++) {
        int e = tid + i * 256;
        const __nv_bfloat16* src = (e < 1024) ? Qh_ : Ql_;
        int idx = e & 1023, row = idx >> 3, seg = idx & 7;
        int off = row * 128 + seg * 16;
        off ^= (off >> 3) & 0x70;
        cpasync16(sb + ((e < 1024) ? 0 : 16384) + off,
                  src + (qrow0 + row) * DM + h * 64 + seg * 8);
    }
    auto issue_kv = [&](int c) {
        int kv0 = c * 64;
        uint32_t base = sb + AQ + (c & 1) * ABUF;
        size_t krow0 = (size_t)b * SEQ + kv0;
#pragma unroll
        for (int i = 0; i < 8; i++) {
            int e = tid + i * 256;
            int t = e >> 9, idx = e & 511, row = idx >> 3, seg = idx & 7;
            const __nv_bfloat16* src = (t == 0) ? Kh_ : (t == 1) ? Kl_ : (t == 2) ? Vh_ : Vl_;
            int off = row * 128 + seg * 16;
            off ^= (off >> 3) & 0x70;
            cpasync16(base + t * 8192 + off, src + (krow0 + row) * DM + h * 64 + seg * 8);
        }
        if (tid < 128)
            cpasync8(base + 32768 + tid * 8,
                     MB + (qrow0 + tid) * (SEQ / 8) + (kv0 >> 3));
    };
    issue_kv(0); CP_COMMIT();
    issue_kv(1); CP_COMMIT();

    float s[8][4], o[8][4];
    float m0 = -1e30f, m1 = -1e30f, l0 = 0.0f, l1 = 0.0f;
#pragma unroll
    for (int nt = 0; nt < 8; nt++)
#pragma unroll
        for (int e = 0; e < 4; e++) o[nt][e] = 0.0f;

    int a_lrow = lane & 15, a_kadd = (lane < 16) ? 0 : 16;
    int b_lrow = lane & 7, b_kadd = ((lane & 15) >= 8) ? 16 : 0;
    const int NT = SEQ / 64;

    for (int c = 0; c < NT; c++) {
        if (c + 1 < NT) { issue_kv(c + 1); CP_COMMIT(); CP_WAIT(1); }
        else CP_WAIT(0);
        __syncthreads();
        uint32_t base = sb + AQ + (c & 1) * ABUF;
        const char* bufp = sm + AQ + (c & 1) * ABUF;

#pragma unroll
        for (int nt = 0; nt < 8; nt++)
#pragma unroll
            for (int e = 0; e < 4; e++) s[nt][e] = 0.0f;

#pragma unroll
        for (int ks = 0; ks < 4; ks++) {
            uint32_t qh[4], ql[4];
            int aoff = (w * 16 + a_lrow) * 128 + ks * 32 + a_kadd;
            aoff ^= (aoff >> 3) & 0x70;
            ldm_x4(qh, sb + aoff);
            ldm_x4(ql, sb + 16384 + aoff);
#pragma unroll
            for (int nt = 0; nt < 8; nt++) {
                int boff = (nt * 8 + b_lrow) * 128 + ks * 32 + b_kadd;
                boff ^= (boff >> 3) & 0x70;
                uint32_t kh[2], kl[2];
                ldm_x2(kh, base + boff);
                ldm_x2(kl, base + 8192 + boff);
                mma16816(s[nt], qh, kh);
                mma16816(s[nt], qh, kl);
                mma16816(s[nt], ql, kh);
            }
        }

        unsigned long long bits0 = *(const unsigned long long*)(bufp + 32768 + (w * 16 + quad) * 8);
        unsigned long long bits1 = *(const unsigned long long*)(bufp + 32768 + (w * 16 + quad + 8) * 8);
#pragma unroll
        for (int nt = 0; nt < 8; nt++)
#pragma unroll
            for (int e = 0; e < 4; e++) s[nt][e] *= scale;
        if (bits0) {
#pragma unroll
            for (int nt = 0; nt < 8; nt++) {
                if ((bits0 >> (nt * 8 + 2 * pos)) & 1)     s[nt][0] = -1e9f;
                if ((bits0 >> (nt * 8 + 2 * pos + 1)) & 1) s[nt][1] = -1e9f;
            }
        }
        if (bits1) {
#pragma unroll
            for (int nt = 0; nt < 8; nt++) {
                if ((bits1 >> (nt * 8 + 2 * pos)) & 1)     s[nt][2] = -1e9f;
                if ((bits1 >> (nt * 8 + 2 * pos + 1)) & 1) s[nt][3] = -1e9f;
            }
        }
        float mm0 = -1e30f, mm1 = -1e30f;
#pragma unroll
        for (int nt = 0; nt < 8; nt++) {
            mm0 = fmaxf(mm0, fmaxf(s[nt][0], s[nt][1]));
            mm1 = fmaxf(mm1, fmaxf(s[nt][2], s[nt][3]));
        }
        mm0 = fmaxf(mm0, __shfl_xor_sync(0xffffffffu, mm0, 1));
        mm0 = fmaxf(mm0, __shfl_xor_sync(0xffffffffu, mm0, 2));
        mm1 = fmaxf(mm1, __shfl_xor_sync(0xffffffffu, mm1, 1));
        mm1 = fmaxf(mm1, __shfl_xor_sync(0xffffffffu, mm1, 2));
        float mn0 = fmaxf(m0, mm0), mn1 = fmaxf(m1, mm1);
        float c0 = __expf(m0 - mn0), c1 = __expf(m1 - mn1);
        float ls0 = 0.0f, ls1 = 0.0f;
#pragma unroll
        for (int nt = 0; nt < 8; nt++) {
            s[nt][0] = __expf(s[nt][0] - mn0);
            s[nt][1] = __expf(s[nt][1] - mn0);
            s[nt][2] = __expf(s[nt][2] - mn1);
            s[nt][3] = __expf(s[nt][3] - mn1);
            ls0 += s[nt][0] + s[nt][1];
            ls1 += s[nt][2] + s[nt][3];
        }
        ls0 += __shfl_xor_sync(0xffffffffu, ls0, 1);
        ls0 += __shfl_xor_sync(0xffffffffu, ls0, 2);
        ls1 += __shfl_xor_sync(0xffffffffu, ls1, 1);
        ls1 += __shfl_xor_sync(0xffffffffu, ls1, 2);
        l0 = l0 * c0 + ls0; l1 = l1 * c1 + ls1;
        m0 = mn0; m1 = mn1;
#pragma unroll
        for (int nt = 0; nt < 8; nt++) {
            o[nt][0] *= c0; o[nt][1] *= c0;
            o[nt][2] *= c1; o[nt][3] *= c1;
        }

#pragma unroll
        for (int ks = 0; ks < 4; ks++) {
            uint32_t ah[4], al[4];
            pack_hl(s[2 * ks][0],     s[2 * ks][1],     ah[0], al[0]);
            pack_hl(s[2 * ks][2],     s[2 * ks][3],     ah[1], al[1]);
            pack_hl(s[2 * ks + 1][0], s[2 * ks + 1][1], ah[2], al[2]);
            pack_hl(s[2 * ks + 1][2], s[2 * ks + 1][3], ah[3], al[3]);
#pragma unroll
            for (int nt = 0; nt < 8; nt++) {
                int voff = (ks * 16 + (lane & 15)) * 128 + nt * 16;
                voff ^= (voff >> 3) & 0x70;
                uint32_t vh[2], vl[2];
                ldm_x2t(vh, base + 16384 + voff);
                ldm_x2t(vl, base + 24576 + voff);
                mma16816(o[nt], ah, vh);
                mma16816(o[nt], ah, vl);
                mma16816(o[nt], al, vh);
            }
        }
        __syncthreads();
    }

    float i0 = 1.0f / l0, i1 = 1.0f / l1;
    size_t r0g = qrow0 + w * 16 + quad, r1g = r0g + 8;
#pragma unroll
    for (int nt = 0; nt < 8; nt++) {
        int col = h * 64 + nt * 8 + 2 * pos;
        uint32_t hw, lw;
        pack_hl(o[nt][0] * i0, o[nt][1] * i0, hw, lw);
        ((uint32_t*)Ch_)[(r0g * DM + col) >> 1] = hw;
        ((uint32_t*)Cl_)[(r0g * DM + col) >> 1] = lw;
        pack_hl(o[nt][2] * i1, o[nt][3] * i1, hw, lw);
        ((uint32_t*)Ch_)[(r1g * DM + col) >> 1] = hw;
        ((uint32_t*)Cl_)[(r1g * DM + col) >> 1] = lw;
    }
}

// ---------------- layernorm (biased var), optional bf16 split out ---------
template <int SPLIT>
__global__ __launch_bounds__(256) void layernorm_kernel(
    const float* __restrict__ X, const float* __restrict__ g,
    const float* __restrict__ bt, float* __restrict__ out,
    __nv_bfloat16* __restrict__ Oh, __nv_bfloat16* __restrict__ Ol)
{
    __shared__ float sh_s[8], sh_ss[8], sh_m, sh_r;
    int row = blockIdx.x, tid = threadIdx.x;
    const float* x = X + (size_t)row * DM;
    float4 xv = *(const float4*)&x[tid * 4];
    float s = xv.x + xv.y + xv.z + xv.w;
    float ss = xv.x * xv.x + xv.y * xv.y + xv.z * xv.z + xv.w * xv.w;
#pragma unroll
    for (int off = 16; off; off >>= 1) {
        s += __shfl_xor_sync(0xffffffffu, s, off);
        ss += __shfl_xor_sync(0xffffffffu, ss, off);
    }
    int wid = tid >> 5, lane = tid & 31;
    if (lane == 0) { sh_s[wid] = s; sh_ss[wid] = ss; }
    __syncthreads();
    if (wid == 0) {
        float s2 = (lane < 8) ? sh_s[lane] : 0.0f;
        float ss2 = (lane < 8) ? sh_ss[lane] : 0.0f;
#pragma unroll
        for (int off = 4; off; off >>= 1) {
            s2 += __shfl_xor_sync(0xffffffffu, s2, off);
            ss2 += __shfl_xor_sync(0xffffffffu, ss2, off);
        }
        if (lane == 0) {
            float mean = s2 * (1.0f / DM);
            sh_m = mean;
            sh_r = rsqrtf(ss2 * (1.0f / DM) - mean * mean + 1e-5f);
        }
    }
    __syncthreads();
    float mean = sh_m, rstd = sh_r;
    float4 gv = *(const float4*)&g[tid * 4];
    float4 bv = *(const float4*)&bt[tid * 4];
    float4 ov;
    ov.x = (xv.x - mean) * rstd * gv.x + bv.x;
    ov.y = (xv.y - mean) * rstd * gv.y + bv.y;
    ov.z = (xv.z - mean) * rstd * gv.z + bv.z;
    ov.w = (xv.w - mean) * rstd * gv.w + bv.w;
    *(float4*)&out[(size_t)row * DM + tid * 4] = ov;
    if (SPLIT) {
        uint32_t h0, l0, h1, l1;
        pack_hl(ov.x, ov.y, h0, l0);
        pack_hl(ov.z, ov.w, h1, l1);
        size_t base = ((size_t)row * DM + tid * 4) >> 1;
        ((uint32_t*)Oh)[base] = h0; ((uint32_t*)Oh)[base + 1] = h1;
        ((uint32_t*)Ol)[base] = l0; ((uint32_t*)Ol)[base + 1] = l1;
    }
}

// -------------------------------- host -----------------------------------
extern "C" void kernel_launch(void* const* d_in, const int* in_sizes, int n_in,
                              void* d_out, int out_size)
{
    const float* X = (const float*)d_in[0];
    const unsigned char* mask = (const unsigned char*)d_in[1];
    const float *Wq = (const float*)d_in[2], *bq = (const float*)d_in[3];
    const float *Wk = (const float*)d_in[4], *bk = (const float*)d_in[5];
    const float *Wv = (const float*)d_in[6], *bv = (const float*)d_in[7];
    const float *Wo = (const float*)d_in[8], *bo = (const float*)d_in[9];
    const float *g1 = (const float*)d_in[10], *b1 = (const float*)d_in[11];
    const float *W1 = (const float*)d_in[12], *bf1 = (const float*)d_in[13];
    const float *W2 = (const float*)d_in[14], *bf2 = (const float*)d_in[15];
    const float *g2 = (const float*)d_in[16], *b2 = (const float*)d_in[17];
    float* out = (float*)d_out;

    float *T1p, *AOp;
    cudaGetSymbolAddress((void**)&T1p, g_T1);
    cudaGetSymbolAddress((void**)&AOp, g_AO);
    __nv_bfloat16 *Xh, *Xl, *Qh, *Ql, *Kh, *Kl, *Vh, *Vl, *Ch, *Cl, *AOh, *AOl, *Hh, *Hl, *Wh, *Wl;
    cudaGetSymbolAddress((void**)&Xh, g_Xh);  cudaGetSymbolAddress((void**)&Xl, g_Xl);
    cudaGetSymbolAddress((void**)&Qh, g_Qh);  cudaGetSymbolAddress((void**)&Ql, g_Ql);
    cudaGetSymbolAddress((void**)&Kh, g_Kh);  cudaGetSymbolAddress((void**)&Kl, g_Kl);
    cudaGetSymbolAddress((void**)&Vh, g_Vh);  cudaGetSymbolAddress((void**)&Vl, g_Vl);
    cudaGetSymbolAddress((void**)&Ch, g_Ch);  cudaGetSymbolAddress((void**)&Cl, g_Cl);
    cudaGetSymbolAddress((void**)&AOh, g_AOh); cudaGetSymbolAddress((void**)&AOl, g_AOl);
    cudaGetSymbolAddress((void**)&Hh, g_Hh);  cudaGetSymbolAddress((void**)&Hl, g_Hl);
    cudaGetSymbolAddress((void**)&Wh, g_Wh);  cudaGetSymbolAddress((void**)&Wl, g_Wl);
    unsigned char* MBp;
    cudaGetSymbolAddress((void**)&MBp, g_MB);

    const size_t S1 = (size_t)DM * DM;
    __nv_bfloat16 *oh = Wh + 3 * S1, *ol = Wl + 3 * S1;
    __nv_bfloat16 *w1h = Wh + 4 * S1, *w2h = Wh + 4 * S1 + (size_t)DM * DFF;
    __nv_bfloat16 *w1l = Wl + 4 * S1, *w2l = Wl + 4 * S1 + (size_t)DM * DFF;

    cudaFuncSetAttribute(gemm_qkv_kernel, cudaFuncAttributeMaxDynamicSharedMemorySize, SM_TOT);
    cudaFuncSetAttribute(gemm3_kernel<1, 1>, cudaFuncAttributeMaxDynamicSharedMemorySize, SM_TOT);
    cudaFuncSetAttribute(gemm3_kernel<2, 0>, cudaFuncAttributeMaxDynamicSharedMemorySize, SM_TOT);
    cudaFuncSetAttribute(attn_kernel, cudaFuncAttributeMaxDynamicSharedMemorySize, ASM);

    dim3 tb(32, 8);
    // launch order matters: ncu profiles launch index 5 (-s 5 -c 1) -> attn
    splitT3_kernel<<<dim3(DM / 32, DM / 32, 3), tb>>>(Wq, Wk, Wv, Wh, Wl);      // 0
    maskbits_kernel<<<(BATCH * SEQ * SEQ / 8) / 256, 256>>>(mask, MBp);         // 1
    split_kernel<<<(TOKENS * DM) / 1024, 256>>>((const float4*)X, Xh, Xl);      // 2
    splitT_kernel<<<dim3(DM / 32, DM / 32), tb>>>(Wo, oh, ol, DM, DM);          // 3

    dim3 gproj(DM / 128, TOKENS / 128), gff1(DFF / 128, TOKENS / 128);
    dim3 gqkv(3 * DM / 128, TOKENS / 128);
    gemm_qkv_kernel<<<gqkv, 256, SM_TOT>>>(Xh, Xl, Wh, Wl, bq, bk, bv,          // 4
                                           Qh, Ql, Kh, Kl, Vh, Vl);

    dim3 gattn(SEQ / 128, HEADS, BATCH);
    attn_kernel<<<gattn, 256, ASM>>>(Qh, Ql, Kh, Kl, Vh, Vl, MBp, Ch, Cl);      // 5 <- profiled

    splitT_kernel<<<dim3(DFF / 32, DM / 32), tb>>>(W1, w1h, w1l, DM, DFF);      // 6
    splitT_kernel<<<dim3(DM / 32, DFF / 32), tb>>>(W2, w2h, w2l, DFF, DM);      // 7

    gemm3_kernel<2, 0><<<gproj, 256, SM_TOT>>>(Ch, Cl, oh, ol, bo, X, T1p, nullptr, nullptr, DM, DM);
    layernorm_kernel<1><<<TOKENS, 256>>>(T1p, g1, b1, AOp, AOh, AOl);
    gemm3_kernel<1, 1><<<gff1, 256, SM_TOT>>>(AOh, AOl, w1h, w1l, bf1, nullptr, nullptr, Hh, Hl, DFF, DM);
    gemm3_kernel<2, 0><<<gproj, 256, SM_TOT>>>(Hh, Hl, w2h, w2l, bf2, AOp, T1p, nullptr, nullptr, DM, DFF);
    layernorm_kernel<0><<<TOKENS, 256>>>(T1p, g2, b2, out, nullptr, nullptr);
}

// round 8
// speedup vs baseline: 1.0605x; 1.0605x over previous
#include <cuda_runtime.h>
#include <cuda_bf16.h>
#include <math.h>
#include <stdint.h>

#define TOKENS 4096
#define DM     1024
#define DFF    4096
#define HEADS  16
#define DK     64
#define SEQ    2048
#define BATCH  2

// ---------------- scratch (device globals) --------------------------------
__device__ float g_T1[TOKENS * DM];
__device__ float g_AO[TOKENS * DM];
__device__ __nv_bfloat16 g_Xh[TOKENS * DM],  g_Xl[TOKENS * DM];
__device__ __nv_bfloat16 g_Qh[TOKENS * DM],  g_Ql[TOKENS * DM];
__device__ __nv_bfloat16 g_Kh[TOKENS * DM],  g_Kl[TOKENS * DM];
__device__ __nv_bfloat16 g_Vh[TOKENS * DM],  g_Vl[TOKENS * DM];
__device__ __nv_bfloat16 g_Ch[TOKENS * DM],  g_Cl[TOKENS * DM];
__device__ __nv_bfloat16 g_AOh[TOKENS * DM], g_AOl[TOKENS * DM];
__device__ __nv_bfloat16 g_Hh[TOKENS * DFF], g_Hl[TOKENS * DFF];
__device__ __nv_bfloat16 g_Wh[4 * DM * DM + 2 * DM * DFF];
__device__ __nv_bfloat16 g_Wl[4 * DM * DM + 2 * DM * DFF];
__device__ unsigned char g_MB[BATCH * SEQ * SEQ / 8];

// ---------------- ptx helpers ---------------------------------------------
__device__ __forceinline__ uint32_t smem_u32(const void* p) {
    uint32_t a;
    asm("{ .reg .u64 t; cvta.to.shared.u64 t, %1; cvt.u32.u64 %0, t; }" : "=r"(a) : "l"(p));
    return a;
}
__device__ __forceinline__ void ldm_x4(uint32_t* r, uint32_t a) {
    asm volatile("ldmatrix.sync.aligned.m8n8.x4.shared.b16 {%0,%1,%2,%3}, [%4];"
        : "=r"(r[0]), "=r"(r[1]), "=r"(r[2]), "=r"(r[3]) : "r"(a));
}
__device__ __forceinline__ void ldm_x2(uint32_t* r, uint32_t a) {
    asm volatile("ldmatrix.sync.aligned.m8n8.x2.shared.b16 {%0,%1}, [%2];"
        : "=r"(r[0]), "=r"(r[1]) : "r"(a));
}
__device__ __forceinline__ void ldm_x2t(uint32_t* r, uint32_t a) {
    asm volatile("ldmatrix.sync.aligned.m8n8.x2.trans.shared.b16 {%0,%1}, [%2];"
        : "=r"(r[0]), "=r"(r[1]) : "r"(a));
}
__device__ __forceinline__ void mma16816(float* c, const uint32_t* a, const uint32_t* b) {
    asm volatile("mma.sync.aligned.m16n8k16.row.col.f32.bf16.bf16.f32 "
        "{%0,%1,%2,%3}, {%4,%5,%6,%7}, {%8,%9}, {%0,%1,%2,%3};"
        : "+f"(c[0]), "+f"(c[1]), "+f"(c[2]), "+f"(c[3])
        : "r"(a[0]), "r"(a[1]), "r"(a[2]), "r"(a[3]), "r"(b[0]), "r"(b[1]));
}
__device__ __forceinline__ void cpasync16(uint32_t s, const void* g) {
    asm volatile("cp.async.cg.shared.global [%0], [%1], 16;" :: "r"(s), "l"(g));
}
__device__ __forceinline__ void cpasync8(uint32_t s, const void* g) {
    asm volatile("cp.async.ca.shared.global [%0], [%1], 8;" :: "r"(s), "l"(g));
}
#define CP_COMMIT() asm volatile("cp.async.commit_group;" ::: "memory")
#define CP_WAIT(n)  asm volatile("cp.async.wait_group %0;" :: "n"(n) : "memory")

__device__ __forceinline__ float gelu_exact(float x) {
    return 0.5f * x * (1.0f + erff(x * 0.70710678118654752f));
}
__device__ __forceinline__ void pack_hl(float x, float y, uint32_t& h, uint32_t& l) {
    __nv_bfloat162 hh = __floats2bfloat162_rn(x, y);
    __nv_bfloat162 ll = __floats2bfloat162_rn(x - __bfloat162float(hh.x),
                                              y - __bfloat162float(hh.y));
    h = reinterpret_cast<uint32_t&>(hh);
    l = reinterpret_cast<uint32_t&>(ll);
}

// ---------------- small prep kernels --------------------------------------
__global__ __launch_bounds__(256) void split_kernel(
    const float4* __restrict__ X, __nv_bfloat16* __restrict__ H, __nv_bfloat16* __restrict__ L)
{
    int i = blockIdx.x * 256 + threadIdx.x;
    float4 v = X[i];
    uint32_t h0, l0, h1, l1;
    pack_hl(v.x, v.y, h0, l0);
    pack_hl(v.z, v.w, h1, l1);
    ((uint32_t*)H)[2 * i] = h0; ((uint32_t*)H)[2 * i + 1] = h1;
    ((uint32_t*)L)[2 * i] = l0; ((uint32_t*)L)[2 * i + 1] = l1;
}

__global__ __launch_bounds__(256) void maskbits_kernel(
    const unsigned char* __restrict__ m, unsigned char* __restrict__ bits)
{
    int i = blockIdx.x * 256 + threadIdx.x;
    unsigned long long v = *(const unsigned long long*)(m + 8ull * i);
    unsigned r = 0;
#pragma unroll
    for (int j = 0; j < 8; j++)
        r |= (((v >> (8 * j)) & 0xffull) ? 1u : 0u) << j;
    bits[i] = (unsigned char)r;
}

// W [K,N] fp32 -> Th/Tl [N,K] bf16 (transpose + split)
__global__ void splitT_kernel(const float* __restrict__ W,
    __nv_bfloat16* __restrict__ Th, __nv_bfloat16* __restrict__ Tl, int K, int N)
{
    __shared__ float t[32][33];
    int n0 = blockIdx.x << 5, k0 = blockIdx.y << 5;
    int tx = threadIdx.x, ty = threadIdx.y;
#pragma unroll
    for (int i = 0; i < 4; i++)
        t[ty + 8 * i][tx] = W[(size_t)(k0 + ty + 8 * i) * N + n0 + tx];
    __syncthreads();
#pragma unroll
    for (int i = 0; i < 4; i++) {
        float v = t[tx][ty + 8 * i];
        __nv_bfloat16 hv = __float2bfloat16(v);
        size_t o = (size_t)(n0 + ty + 8 * i) * K + k0 + tx;
        Th[o] = hv;
        Tl[o] = __float2bfloat16(v - __bfloat162float(hv));
    }
}

// ===== mma.sync split-bf16 GEMM: C[M,N] = A@B^T (+epi), B stored [N,K] ====
// BK=64 (128B rows, SW128), 3-stage cp.async pipeline (192KB smem)
#define TILE_B 16384
#define BUF_B  65536
#define SM_TOT 196608
// EPI: 0 bias, 1 bias+gelu, 2 bias+residual.  OM: 0 fp32 C, 1 bf16 hi/lo pair
template <int EPI, int OM>
__global__ __launch_bounds__(256) void gemm3_kernel(
    const __nv_bfloat16* __restrict__ Ah, const __nv_bfloat16* __restrict__ Al,
    const __nv_bfloat16* __restrict__ Bh, const __nv_bfloat16* __restrict__ Bl,
    const float* __restrict__ bias, const float* __restrict__ Rres,
    float* __restrict__ C, __nv_bfloat16* __restrict__ Ch, __nv_bfloat16* __restrict__ Cl,
    int N, int K)
{
    extern __shared__ char gsm[];
    uint32_t sb = smem_u32(gsm);
    int tid = threadIdx.x, wid = tid >> 5, lane = tid & 31;
    int rowBase = blockIdx.y * 128, colBase = blockIdx.x * 128;
    int warp_m = (wid & 1) * 64, warp_n = (wid >> 1) * 32;

    float acc[4][4][4];
#pragma unroll
    for (int i = 0; i < 4; i++)
#pragma unroll
        for (int j = 0; j < 4; j++)
#pragma unroll
            for (int e = 0; e < 4; e++) acc[i][j][e] = 0.0f;

    const int NC = K >> 6;
    auto issue = [&](int c) {
        int k0 = c << 6, buf = c % 3;
#pragma unroll
        for (int i = 0; i < 16; i++) {
            int t = i >> 2;
            int e = ((i & 3) << 8) + tid;
            int row = e >> 3, seg = e & 7;
            const __nv_bfloat16* src = (t == 0) ? Ah : (t == 1) ? Al : (t == 2) ? Bh : Bl;
            int gr = ((t < 2) ? rowBase : colBase) + row;
            int off = row * 128 + seg * 16;
            off ^= (off >> 3) & 0x70;
            cpasync16(sb + buf * BUF_B + t * TILE_B + off,
                      src + (size_t)gr * K + k0 + seg * 8);
        }
        CP_COMMIT();
    };

    issue(0);
    if (NC > 1) issue(1);
    int a_lrow = lane & 15, a_kadd = (lane < 16) ? 0 : 16;
    // B x4 lane mapping: bit3 -> k half, bit4 -> row group (+8)
    int b_row4 = (lane & 7) | (((lane >> 4) & 1) << 3);
    int b_k4 = ((lane >> 3) & 1) * 16;

    for (int c = 0; c < NC; c++) {
        if (c + 2 < NC)      { issue(c + 2); CP_WAIT(2); }
        else if (c + 1 < NC) { CP_WAIT(1); }
        else                 { CP_WAIT(0); }
        __syncthreads();
        uint32_t base = sb + (c % 3) * BUF_B;
#pragma unroll
        for (int ks = 0; ks < 4; ks++) {
            uint32_t aH[4][4], aL[4][4], bH[2][4], bL[2][4];
#pragma unroll
            for (int i = 0; i < 4; i++) {
                int off = (warp_m + 16 * i + a_lrow) * 128 + ks * 32 + a_kadd;
                off ^= (off >> 3) & 0x70;
                ldm_x4(aH[i], base + off);
                ldm_x4(aL[i], base + TILE_B + off);
            }
#pragma unroll
            for (int jp = 0; jp < 2; jp++) {
                int off = (warp_n + 16 * jp + b_row4) * 128 + ks * 32 + b_k4;
                off ^= (off >> 3) & 0x70;
                ldm_x4(bH[jp], base + 2 * TILE_B + off);
                ldm_x4(bL[jp], base + 3 * TILE_B + off);
            }
#pragma unroll
            for (int i = 0; i < 4; i++)
#pragma unroll
                for (int j = 0; j < 4; j++) {
                    const uint32_t* bh = &bH[j >> 1][(j & 1) * 2];
                    const uint32_t* bl = &bL[j >> 1][(j & 1) * 2];
                    mma16816(acc[i][j], aH[i], bh);
                    mma16816(acc[i][j], aH[i], bl);
                    mma16816(acc[i][j], aL[i], bh);
                }
        }
        __syncthreads();
    }

    int quad = lane >> 2, pos = lane & 3;
#pragma unroll
    for (int i = 0; i < 4; i++)
#pragma unroll
        for (int j = 0; j < 4; j++) {
            int col = colBase + warp_n + 8 * j + 2 * pos;
            float2 bz = *(const float2*)&bias[col];
#pragma unroll
            for (int h = 0; h < 2; h++) {
                size_t row = rowBase + warp_m + 16 * i + quad + 8 * h;
                float vx = acc[i][j][2 * h] + bz.x;
                float vy = acc[i][j][2 * h + 1] + bz.y;
                if (EPI == 2) {
                    float2 rv = *(const float2*)&Rres[row * N + col];
                    vx += rv.x; vy += rv.y;
                }
                if (EPI == 1) { vx = gelu_exact(vx); vy = gelu_exact(vy); }
                if (OM == 0) {
                    *(float2*)&C[row * N + col] = make_float2(vx, vy);
                } else {
                    uint32_t hw, lw;
                    pack_hl(vx, vy, hw, lw);
                    ((uint32_t*)Ch)[(row * N + col) >> 1] = hw;
                    ((uint32_t*)Cl)[(row * N + col) >> 1] = lw;
                }
            }
        }
}

// ======== tensor-core flash attention (split bf16, online softmax) ========
#define AQ    32768
#define ABUF  33792
#define ASM   (AQ + 2 * ABUF)
__global__ void __launch_bounds__(256, 2) attn_kernel(
    const __nv_bfloat16* __restrict__ Qh_, const __nv_bfloat16* __restrict__ Ql_,
    const __nv_bfloat16* __restrict__ Kh_, const __nv_bfloat16* __restrict__ Kl_,
    const __nv_bfloat16* __restrict__ Vh_, const __nv_bfloat16* __restrict__ Vl_,
    const unsigned char* __restrict__ MB,
    __nv_bfloat16* __restrict__ Ch_, __nv_bfloat16* __restrict__ Cl_)
{
    extern __shared__ char sm[];
    uint32_t sb = smem_u32(sm);
    int tid = threadIdx.x, w = tid >> 5, lane = tid & 31;
    int quad = lane >> 2, pos = lane & 3;
    int q0 = blockIdx.x * 128, h = blockIdx.y, b = blockIdx.z;
    size_t qrow0 = (size_t)b * SEQ + q0;
    const float scale = 0.125f;

#pragma unroll
    for (int i = 0; i < 8; i++) {
        int e = tid + i * 256;
        const __nv_bfloat16* src = (e < 1024) ? Qh_ : Ql_;
        int idx = e & 1023, row = idx >> 3, seg = idx & 7;
        int off = row * 128 + seg * 16;
        off ^= (off >> 3) & 0x70;
        cpasync16(sb + ((e < 1024) ? 0 : 16384) + off,
                  src + (qrow0 + row) * DM + h * 64 + seg * 8);
    }
    auto issue_kv = [&](int c) {
        int kv0 = c * 64;
        uint32_t base = sb + AQ + (c & 1) * ABUF;
        size_t krow0 = (size_t)b * SEQ + kv0;
#pragma unroll
        for (int i = 0; i < 8; i++) {
            int e = tid + i * 256;
            int t = e >> 9, idx = e & 511, row = idx >> 3, seg = idx & 7;
            const __nv_bfloat16* src = (t == 0) ? Kh_ : (t == 1) ? Kl_ : (t == 2) ? Vh_ : Vl_;
            int off = row * 128 + seg * 16;
            off ^= (off >> 3) & 0x70;
            cpasync16(base + t * 8192 + off, src + (krow0 + row) * DM + h * 64 + seg * 8);
        }
        if (tid < 128)
            cpasync8(base + 32768 + tid * 8,
                     MB + (qrow0 + tid) * (SEQ / 8) + (kv0 >> 3));
    };
    issue_kv(0); CP_COMMIT();
    issue_kv(1); CP_COMMIT();

    float s[8][4], o[8][4];
    float m0 = -1e30f, m1 = -1e30f, l0 = 0.0f, l1 = 0.0f;
#pragma unroll
    for (int nt = 0; nt < 8; nt++)
#pragma unroll
        for (int e = 0; e < 4; e++) o[nt][e] = 0.0f;

    int a_lrow = lane & 15, a_kadd = (lane < 16) ? 0 : 16;
    int b_lrow = lane & 7, b_kadd = ((lane & 15) >= 8) ? 16 : 0;
    const int NT = SEQ / 64;

    for (int c = 0; c < NT; c++) {
        if (c + 1 < NT) { issue_kv(c + 1); CP_COMMIT(); CP_WAIT(1); }
        else CP_WAIT(0);
        __syncthreads();
        uint32_t base = sb + AQ + (c & 1) * ABUF;
        const char* bufp = sm + AQ + (c & 1) * ABUF;

#pragma unroll
        for (int nt = 0; nt < 8; nt++)
#pragma unroll
            for (int e = 0; e < 4; e++) s[nt][e] = 0.0f;

#pragma unroll
        for (int ks = 0; ks < 4; ks++) {
            uint32_t qh[4], ql[4];
            int aoff = (w * 16 + a_lrow) * 128 + ks * 32 + a_kadd;
            aoff ^= (aoff >> 3) & 0x70;
            ldm_x4(qh, sb + aoff);
            ldm_x4(ql, sb + 16384 + aoff);
#pragma unroll
            for (int nt = 0; nt < 8; nt++) {
                int boff = (nt * 8 + b_lrow) * 128 + ks * 32 + b_kadd;
                boff ^= (boff >> 3) & 0x70;
                uint32_t kh[2], kl[2];
                ldm_x2(kh, base + boff);
                ldm_x2(kl, base + 8192 + boff);
                mma16816(s[nt], qh, kh);
                mma16816(s[nt], qh, kl);
                mma16816(s[nt], ql, kh);
            }
        }

        unsigned long long bits0 = *(const unsigned long long*)(bufp + 32768 + (w * 16 + quad) * 8);
        unsigned long long bits1 = *(const unsigned long long*)(bufp + 32768 + (w * 16 + quad + 8) * 8);
#pragma unroll
        for (int nt = 0; nt < 8; nt++)
#pragma unroll
            for (int e = 0; e < 4; e++) s[nt][e] *= scale;
        if (bits0) {
#pragma unroll
            for (int nt = 0; nt < 8; nt++) {
                if ((bits0 >> (nt * 8 + 2 * pos)) & 1)     s[nt][0] = -1e9f;
                if ((bits0 >> (nt * 8 + 2 * pos + 1)) & 1) s[nt][1] = -1e9f;
            }
        }
        if (bits1) {
#pragma unroll
            for (int nt = 0; nt < 8; nt++) {
                if ((bits1 >> (nt * 8 + 2 * pos)) & 1)     s[nt][2] = -1e9f;
                if ((bits1 >> (nt * 8 + 2 * pos + 1)) & 1) s[nt][3] = -1e9f;
            }
        }
        float mm0 = -1e30f, mm1 = -1e30f;
#pragma unroll
        for (int nt = 0; nt < 8; nt++) {
            mm0 = fmaxf(mm0, fmaxf(s[nt][0], s[nt][1]));
            mm1 = fmaxf(mm1, fmaxf(s[nt][2], s[nt][3]));
        }
        mm0 = fmaxf(mm0, __shfl_xor_sync(0xffffffffu, mm0, 1));
        mm0 = fmaxf(mm0, __shfl_xor_sync(0xffffffffu, mm0, 2));
        mm1 = fmaxf(mm1, __shfl_xor_sync(0xffffffffu, mm1, 1));
        mm1 = fmaxf(mm1, __shfl_xor_sync(0xffffffffu, mm1, 2));
        float mn0 = fmaxf(m0, mm0), mn1 = fmaxf(m1, mm1);
        float c0 = __expf(m0 - mn0), c1 = __expf(m1 - mn1);
        float ls0 = 0.0f, ls1 = 0.0f;
#pragma unroll
        for (int nt = 0; nt < 8; nt++) {
            s[nt][0] = __expf(s[nt][0] - mn0);
            s[nt][1] = __expf(s[nt][1] - mn0);
            s[nt][2] = __expf(s[nt][2] - mn1);
            s[nt][3] = __expf(s[nt][3] - mn1);
            ls0 += s[nt][0] + s[nt][1];
            ls1 += s[nt][2] + s[nt][3];
        }
        ls0 += __shfl_xor_sync(0xffffffffu, ls0, 1);
        ls0 += __shfl_xor_sync(0xffffffffu, ls0, 2);
        ls1 += __shfl_xor_sync(0xffffffffu, ls1, 1);
        ls1 += __shfl_xor_sync(0xffffffffu, ls1, 2);
        l0 = l0 * c0 + ls0; l1 = l1 * c1 + ls1;
        m0 = mn0; m1 = mn1;
#pragma unroll
        for (int nt = 0; nt < 8; nt++) {
            o[nt][0] *= c0; o[nt][1] *= c0;
            o[nt][2] *= c1; o[nt][3] *= c1;
        }

#pragma unroll
        for (int ks = 0; ks < 4; ks++) {
            uint32_t ah[4], al[4];
            pack_hl(s[2 * ks][0],     s[2 * ks][1],     ah[0], al[0]);
            pack_hl(s[2 * ks][2],     s[2 * ks][3],     ah[1], al[1]);
            pack_hl(s[2 * ks + 1][0], s[2 * ks + 1][1], ah[2], al[2]);
            pack_hl(s[2 * ks + 1][2], s[2 * ks + 1][3], ah[3], al[3]);
#pragma unroll
            for (int nt = 0; nt < 8; nt++) {
                int voff = (ks * 16 + (lane & 15)) * 128 + nt * 16;
                voff ^= (voff >> 3) & 0x70;
                uint32_t vh[2], vl[2];
                ldm_x2t(vh, base + 16384 + voff);
                ldm_x2t(vl, base + 24576 + voff);
                mma16816(o[nt], ah, vh);
                mma16816(o[nt], ah, vl);
                mma16816(o[nt], al, vh);
            }
        }
        __syncthreads();
    }

    float i0 = 1.0f / l0, i1 = 1.0f / l1;
    size_t r0g = qrow0 + w * 16 + quad, r1g = r0g + 8;
#pragma unroll
    for (int nt = 0; nt < 8; nt++) {
        int col = h * 64 + nt * 8 + 2 * pos;
        uint32_t hw, lw;
        pack_hl(o[nt][0] * i0, o[nt][1] * i0, hw, lw);
        ((uint32_t*)Ch_)[(r0g * DM + col) >> 1] = hw;
        ((uint32_t*)Cl_)[(r0g * DM + col) >> 1] = lw;
        pack_hl(o[nt][2] * i1, o[nt][3] * i1, hw, lw);
        ((uint32_t*)Ch_)[(r1g * DM + col) >> 1] = hw;
        ((uint32_t*)Cl_)[(r1g * DM + col) >> 1] = lw;
    }
}

// ---------------- layernorm (biased var), optional bf16 split out ---------
template <int SPLIT>
__global__ __launch_bounds__(256) void layernorm_kernel(
    const float* __restrict__ X, const float* __restrict__ g,
    const float* __restrict__ bt, float* __restrict__ out,
    __nv_bfloat16* __restrict__ Oh, __nv_bfloat16* __restrict__ Ol)
{
    __shared__ float sh_s[8], sh_ss[8], sh_m, sh_r;
    int row = blockIdx.x, tid = threadIdx.x;
    const float* x = X + (size_t)row * DM;
    float4 xv = *(const float4*)&x[tid * 4];
    float s = xv.x + xv.y + xv.z + xv.w;
    float ss = xv.x * xv.x + xv.y * xv.y + xv.z * xv.z + xv.w * xv.w;
#pragma unroll
    for (int off = 16; off; off >>= 1) {
        s += __shfl_xor_sync(0xffffffffu, s, off);
        ss += __shfl_xor_sync(0xffffffffu, ss, off);
    }
    int wid = tid >> 5, lane = tid & 31;
    if (lane == 0) { sh_s[wid] = s; sh_ss[wid] = ss; }
    __syncthreads();
    if (wid == 0) {
        float s2 = (lane < 8) ? sh_s[lane] : 0.0f;
        float ss2 = (lane < 8) ? sh_ss[lane] : 0.0f;
#pragma unroll
        for (int off = 4; off; off >>= 1) {
            s2 += __shfl_xor_sync(0xffffffffu, s2, off);
            ss2 += __shfl_xor_sync(0xffffffffu, ss2, off);
        }
        if (lane == 0) {
            float mean = s2 * (1.0f / DM);
            sh_m = mean;
            sh_r = rsqrtf(ss2 * (1.0f / DM) - mean * mean + 1e-5f);
        }
    }
    __syncthreads();
    float mean = sh_m, rstd = sh_r;
    float4 gv = *(const float4*)&g[tid * 4];
    float4 bv = *(const float4*)&bt[tid * 4];
    float4 ov;
    ov.x = (xv.x - mean) * rstd * gv.x + bv.x;
    ov.y = (xv.y - mean) * rstd * gv.y + bv.y;
    ov.z = (xv.z - mean) * rstd * gv.z + bv.z;
    ov.w = (xv.w - mean) * rstd * gv.w + bv.w;
    *(float4*)&out[(size_t)row * DM + tid * 4] = ov;
    if (SPLIT) {
        uint32_t h0, l0, h1, l1;
        pack_hl(ov.x, ov.y, h0, l0);
        pack_hl(ov.z, ov.w, h1, l1);
        size_t base = ((size_t)row * DM + tid * 4) >> 1;
        ((uint32_t*)Oh)[base] = h0; ((uint32_t*)Oh)[base + 1] = h1;
        ((uint32_t*)Ol)[base] = l0; ((uint32_t*)Ol)[base + 1] = l1;
    }
}

// -------------------------------- host -----------------------------------
extern "C" void kernel_launch(void* const* d_in, const int* in_sizes, int n_in,
                              void* d_out, int out_size)
{
    const float* X = (const float*)d_in[0];
    const unsigned char* mask = (const unsigned char*)d_in[1];
    const float *Wq = (const float*)d_in[2], *bq = (const float*)d_in[3];
    const float *Wk = (const float*)d_in[4], *bk = (const float*)d_in[5];
    const float *Wv = (const float*)d_in[6], *bv = (const float*)d_in[7];
    const float *Wo = (const float*)d_in[8], *bo = (const float*)d_in[9];
    const float *g1 = (const float*)d_in[10], *b1 = (const float*)d_in[11];
    const float *W1 = (const float*)d_in[12], *bf1 = (const float*)d_in[13];
    const float *W2 = (const float*)d_in[14], *bf2 = (const float*)d_in[15];
    const float *g2 = (const float*)d_in[16], *b2 = (const float*)d_in[17];
    float* out = (float*)d_out;

    float *T1p, *AOp;
    cudaGetSymbolAddress((void**)&T1p, g_T1);
    cudaGetSymbolAddress((void**)&AOp, g_AO);
    __nv_bfloat16 *Xh, *Xl, *Qh, *Ql, *Kh, *Kl, *Vh, *Vl, *Ch, *Cl, *AOh, *AOl, *Hh, *Hl, *Wh, *Wl;
    cudaGetSymbolAddress((void**)&Xh, g_Xh);  cudaGetSymbolAddress((void**)&Xl, g_Xl);
    cudaGetSymbolAddress((void**)&Qh, g_Qh);  cudaGetSymbolAddress((void**)&Ql, g_Ql);
    cudaGetSymbolAddress((void**)&Kh, g_Kh);  cudaGetSymbolAddress((void**)&Kl, g_Kl);
    cudaGetSymbolAddress((void**)&Vh, g_Vh);  cudaGetSymbolAddress((void**)&Vl, g_Vl);
    cudaGetSymbolAddress((void**)&Ch, g_Ch);  cudaGetSymbolAddress((void**)&Cl, g_Cl);
    cudaGetSymbolAddress((void**)&AOh, g_AOh); cudaGetSymbolAddress((void**)&AOl, g_AOl);
    cudaGetSymbolAddress((void**)&Hh, g_Hh);  cudaGetSymbolAddress((void**)&Hl, g_Hl);
    cudaGetSymbolAddress((void**)&Wh, g_Wh);  cudaGetSymbolAddress((void**)&Wl, g_Wl);
    unsigned char* MBp;
    cudaGetSymbolAddress((void**)&MBp, g_MB);

    const size_t S1 = (size_t)DM * DM;
    __nv_bfloat16 *qh = Wh, *kh = Wh + S1, *vh = Wh + 2 * S1, *oh = Wh + 3 * S1;
    __nv_bfloat16 *w1h = Wh + 4 * S1, *w2h = Wh + 4 * S1 + (size_t)DM * DFF;
    __nv_bfloat16 *ql = Wl, *kl = Wl + S1, *vl = Wl + 2 * S1, *ol = Wl + 3 * S1;
    __nv_bfloat16 *w1l = Wl + 4 * S1, *w2l = Wl + 4 * S1 + (size_t)DM * DFF;

    cudaFuncSetAttribute(gemm3_kernel<0, 1>, cudaFuncAttributeMaxDynamicSharedMemorySize, SM_TOT);
    cudaFuncSetAttribute(gemm3_kernel<1, 1>, cudaFuncAttributeMaxDynamicSharedMemorySize, SM_TOT);
    cudaFuncSetAttribute(gemm3_kernel<2, 0>, cudaFuncAttributeMaxDynamicSharedMemorySize, SM_TOT);
    cudaFuncSetAttribute(attn_kernel, cudaFuncAttributeMaxDynamicSharedMemorySize, ASM);

    dim3 tb(32, 8);
    splitT_kernel<<<dim3(DM / 32, DM / 32), tb>>>(Wq, qh, ql, DM, DM);
    splitT_kernel<<<dim3(DM / 32, DM / 32), tb>>>(Wk, kh, kl, DM, DM);
    splitT_kernel<<<dim3(DM / 32, DM / 32), tb>>>(Wv, vh, vl, DM, DM);
    splitT_kernel<<<dim3(DM / 32, DM / 32), tb>>>(Wo, oh, ol, DM, DM);
    splitT_kernel<<<dim3(DFF / 32, DM / 32), tb>>>(W1, w1h, w1l, DM, DFF);
    splitT_kernel<<<dim3(DM / 32, DFF / 32), tb>>>(W2, w2h, w2l, DFF, DM);
    maskbits_kernel<<<(BATCH * SEQ * SEQ / 8) / 256, 256>>>(mask, MBp);
    split_kernel<<<(TOKENS * DM) / 1024, 256>>>((const float4*)X, Xh, Xl);

    dim3 gproj(DM / 128, TOKENS / 128), gff1(DFF / 128, TOKENS / 128);

    // QKV projections -> bf16 hi/lo directly
    gemm3_kernel<0, 1><<<gproj, 256, SM_TOT>>>(Xh, Xl, qh, ql, bq, nullptr, nullptr, Qh, Ql, DM, DM);
    gemm3_kernel<0, 1><<<gproj, 256, SM_TOT>>>(Xh, Xl, kh, kl, bk, nullptr, nullptr, Kh, Kl, DM, DM);
    gemm3_kernel<0, 1><<<gproj, 256, SM_TOT>>>(Xh, Xl, vh, vl, bv, nullptr, nullptr, Vh, Vl, DM, DM);

    // attention -> CTX bf16 hi/lo
    dim3 gattn(SEQ / 128, HEADS, BATCH);
    attn_kernel<<<gattn, 256, ASM>>>(Qh, Ql, Kh, Kl, Vh, Vl, MBp, Ch, Cl);

    // Wo + residual(X) -> T1 fp32; LN1 -> AO fp32 + hi/lo
    gemm3_kernel<2, 0><<<gproj, 256, SM_TOT>>>(Ch, Cl, oh, ol, bo, X, T1p, nullptr, nullptr, DM, DM);
    layernorm_kernel<1><<<TOKENS, 256>>>(T1p, g1, b1, AOp, AOh, AOl);

    // FF1 + gelu -> H bf16 hi/lo
    gemm3_kernel<1, 1><<<gff1, 256, SM_TOT>>>(AOh, AOl, w1h, w1l, bf1, nullptr, nullptr, Hh, Hl, DFF, DM);

    // FF2 + residual(AO) -> T1; LN2 -> out
    gemm3_kernel<2, 0><<<gproj, 256, SM_TOT>>>(Hh, Hl, w2h, w2l, bf2, AOp, T1p, nullptr, nullptr, DM, DFF);
    layernorm_kernel<0><<<TOKENS, 256>>>(T1p, g2, b2, out, nullptr, nullptr);
}